// round 3
// baseline (speedup 1.0000x reference)
#include <cuda_runtime.h>
#include <math.h>

#define BSZ 4
#define SEQ 2048
#define DIMX 2048
#define NH 16
#define HD 128
#define TOK (BSZ*SEQ)   // 8192

// ---------------- scratch (device globals; no cudaMalloc allowed) ----------
__device__ float g_q[BSZ*NH*SEQ*HD];   // [b][h][s][d]
__device__ float g_k[BSZ*NH*SEQ*HD];
__device__ float g_v[BSZ*NH*SEQ*HD];
__device__ float g_y[TOK*DIMX];        // attention output, [token][dim]

// ---------------- generic SGEMM: C[m][n] = sum_k A[m][k]*B[n][k] ----------
// mode 0: plain store into C.  mode 1: scatter qkv into g_q/g_k/g_v.
// A==nullptr means "use g_y as A" (device-symbol workaround).
#define BM 128
#define BN 128
#define BK 16

__global__ __launch_bounds__(256, 2)
void sgemm_kernel(const float* __restrict__ A, const float* __restrict__ B,
                  float* __restrict__ C, int M, int N, int K, int mode)
{
    __shared__ __align__(16) float As[BK][BM + 4];
    __shared__ __align__(16) float Bs[BK][BN + 4];
    if (A == nullptr) A = g_y;

    const int tid = threadIdx.x;
    const int m0 = blockIdx.y * BM;
    const int n0 = blockIdx.x * BN;
    const int rb = (tid >> 4) << 3;     // 8 output rows
    const int cb = (tid & 15) << 3;     // 8 output cols

    const int lr = tid >> 2;            // load row 0..63 (and +64)
    const int lc = (tid & 3) << 2;      // load col group (float4)

    const float* Aptr = A + (size_t)m0 * K;
    const float* Bptr = B + (size_t)n0 * K;

    float4 pa0 = *(const float4*)(Aptr + (size_t)lr * K + lc);
    float4 pa1 = *(const float4*)(Aptr + (size_t)(lr + 64) * K + lc);
    float4 pb0 = *(const float4*)(Bptr + (size_t)lr * K + lc);
    float4 pb1 = *(const float4*)(Bptr + (size_t)(lr + 64) * K + lc);

    float acc[8][8];
#pragma unroll
    for (int i = 0; i < 8; i++)
#pragma unroll
        for (int j = 0; j < 8; j++) acc[i][j] = 0.f;

    const int ntiles = K / BK;
    for (int kt = 0; kt < ntiles; kt++) {
        // store prefetched tile (transposed) to smem
        As[lc + 0][lr] = pa0.x; As[lc + 1][lr] = pa0.y;
        As[lc + 2][lr] = pa0.z; As[lc + 3][lr] = pa0.w;
        As[lc + 0][lr + 64] = pa1.x; As[lc + 1][lr + 64] = pa1.y;
        As[lc + 2][lr + 64] = pa1.z; As[lc + 3][lr + 64] = pa1.w;
        Bs[lc + 0][lr] = pb0.x; Bs[lc + 1][lr] = pb0.y;
        Bs[lc + 2][lr] = pb0.z; Bs[lc + 3][lr] = pb0.w;
        Bs[lc + 0][lr + 64] = pb1.x; Bs[lc + 1][lr + 64] = pb1.y;
        Bs[lc + 2][lr + 64] = pb1.z; Bs[lc + 3][lr + 64] = pb1.w;
        __syncthreads();

        if (kt + 1 < ntiles) {
            const int ko = (kt + 1) * BK + lc;
            pa0 = *(const float4*)(Aptr + (size_t)lr * K + ko);
            pa1 = *(const float4*)(Aptr + (size_t)(lr + 64) * K + ko);
            pb0 = *(const float4*)(Bptr + (size_t)lr * K + ko);
            pb1 = *(const float4*)(Bptr + (size_t)(lr + 64) * K + ko);
        }

#pragma unroll
        for (int k = 0; k < BK; k++) {
            float4 a0 = *(const float4*)&As[k][rb];
            float4 a1 = *(const float4*)&As[k][rb + 4];
            float4 b0 = *(const float4*)&Bs[k][cb];
            float4 b1 = *(const float4*)&Bs[k][cb + 4];
            float av[8] = {a0.x, a0.y, a0.z, a0.w, a1.x, a1.y, a1.z, a1.w};
            float bv[8] = {b0.x, b0.y, b0.z, b0.w, b1.x, b1.y, b1.z, b1.w};
#pragma unroll
            for (int i = 0; i < 8; i++)
#pragma unroll
                for (int j = 0; j < 8; j++)
                    acc[i][j] = fmaf(av[i], bv[j], acc[i][j]);
        }
        __syncthreads();
    }

    if (mode == 0) {
#pragma unroll
        for (int i = 0; i < 8; i++) {
            const int m = m0 + rb + i;
            float* cp = C + (size_t)m * N + n0 + cb;
            *(float4*)cp       = make_float4(acc[i][0], acc[i][1], acc[i][2], acc[i][3]);
            *(float4*)(cp + 4) = make_float4(acc[i][4], acc[i][5], acc[i][6], acc[i][7]);
        }
    } else {
        // qkv scatter: n -> (which, h, d); m -> (b, s)
        const int n = n0 + cb;
        const int which = n >> 11;          // /2048
        const int r = n & 2047;
        const int h = r >> 7;
        const int d0 = r & 127;
        float* dst = (which == 0) ? g_q : (which == 1) ? g_k : g_v;
#pragma unroll
        for (int i = 0; i < 8; i++) {
            const int m = m0 + rb + i;
            const int b = m >> 11;
            const int s = m & 2047;
            float* p = dst + (((size_t)(b * NH + h) * SEQ + s) * HD + d0);
            *(float4*)p       = make_float4(acc[i][0], acc[i][1], acc[i][2], acc[i][3]);
            *(float4*)(p + 4) = make_float4(acc[i][4], acc[i][5], acc[i][6], acc[i][7]);
        }
    }
}

// ---------------- RMSNorm + RoPE on q,k (in place) -------------------------
// One warp per (b,h,s) row of 128; first 131072 warps -> q, next -> k.
__global__ void norm_rope_kernel(const float* __restrict__ qw,
                                 const float* __restrict__ kw)
{
    const int NROW = BSZ * NH * SEQ;
    int gw = (blockIdx.x * blockDim.x + threadIdx.x) >> 5;
    int lane = threadIdx.x & 31;
    int tensor = (gw >= NROW);
    int row = tensor ? gw - NROW : gw;
    float* base = (tensor ? g_k : g_q) + (size_t)row * HD;
    const float* w = tensor ? kw : qw;
    const int s = row & (SEQ - 1);

    float4 v = *(const float4*)(base + lane * 4);
    float ss = v.x * v.x + v.y * v.y + v.z * v.z + v.w * v.w;
#pragma unroll
    for (int off = 16; off; off >>= 1)
        ss += __shfl_xor_sync(0xffffffffu, ss, off);
    const float inv = rsqrtf(ss * (1.0f / HD) + 1e-6f);

    const float4 wv = *(const float4*)(w + lane * 4);
    float xv[4];
    xv[0] = v.x * inv * wv.x; xv[1] = v.y * inv * wv.y;
    xv[2] = v.z * inv * wv.z; xv[3] = v.w * inv * wv.w;

    float ov[4];
#pragma unroll
    for (int u = 0; u < 4; u++) {
        float other = __shfl_xor_sync(0xffffffffu, xv[u], 16);
        int i = ((lane & 15) << 2) + u;               // freq index 0..63
        float freq = exp2f(-5.0f * (float)i * (1.0f / 64.0f));  // 32^(-i/64)
        float ang = (float)s * freq;
        float sn, cs;
        sincosf(ang, &sn, &cs);
        ov[u] = (lane < 16) ? (xv[u] * cs - other * sn)
                            : (xv[u] * cs + other * sn);
    }
    *(float4*)(base + lane * 4) = make_float4(ov[0], ov[1], ov[2], ov[3]);
}

// ---------------- flash attention -----------------------------------------
// grid: (S/64 q-tiles, B*H). block 256. Q tile 64x128, KV tiles 64x128,
// online softmax. Thread (ty,tx): S frag 4x4 (rows ty*4, cols tx*4),
// O frag 4x8 (rows ty*4, cols tx*8).
#define ATTN_SMEM_FLOATS (128*68 + 128*68 + 64*68)

__global__ __launch_bounds__(256, 2)
void attn_kernel()
{
    extern __shared__ __align__(16) float sm[];
    float* Qt = sm;                 // [k:128][r:64] pad 68, pre-scaled
    float* KV = sm + 128 * 68;      // K phase: [k:128][c:64] pad 68; V phase: [kv:64][d:128] pad 132
    float* Pt = KV + 128 * 68;      // [kvcol:64][r:64] pad 68

    const int tid = threadIdx.x;
    const int q0 = blockIdx.x * 64;
    const int bh = blockIdx.y;
    const int b = bh >> 4, h = bh & 15;
    const float* Qg = g_q + (size_t)bh * SEQ * HD + (size_t)q0 * HD;
    const float* Kg = g_k + (size_t)bh * SEQ * HD;
    const float* Vg = g_v + (size_t)bh * SEQ * HD;
    const float scale = 0.08838834764831845f;   // 128^-0.5

    // load Q transposed + pre-scale
#pragma unroll
    for (int i = 0; i < 8; i++) {
        int v = tid + i * 256;
        int r = v >> 5;
        int k4 = (v & 31) << 2;
        float4 q4 = *(const float4*)(Qg + r * HD + k4);
        Qt[(k4 + 0) * 68 + r] = q4.x * scale;
        Qt[(k4 + 1) * 68 + r] = q4.y * scale;
        Qt[(k4 + 2) * 68 + r] = q4.z * scale;
        Qt[(k4 + 3) * 68 + r] = q4.w * scale;
    }

    const int ty = tid >> 4, tx = tid & 15;
    float acc[4][8];
    float m_i[4], l_i[4];
#pragma unroll
    for (int i = 0; i < 4; i++) {
        m_i[i] = -1e30f; l_i[i] = 0.f;
#pragma unroll
        for (int c = 0; c < 8; c++) acc[i][c] = 0.f;
    }

    for (int kt = 0; kt < SEQ / 64; kt++) {
        // K tile -> transposed smem
        const float* Kt_g = Kg + (size_t)kt * 64 * HD;
#pragma unroll
        for (int i = 0; i < 8; i++) {
            int v = tid + i * 256;
            int r = v >> 5;
            int k4 = (v & 31) << 2;
            float4 kk = *(const float4*)(Kt_g + r * HD + k4);
            KV[(k4 + 0) * 68 + r] = kk.x;
            KV[(k4 + 1) * 68 + r] = kk.y;
            KV[(k4 + 2) * 68 + r] = kk.z;
            KV[(k4 + 3) * 68 + r] = kk.w;
        }
        __syncthreads();

        // S = Q K^T  (64x64, K=128)
        float sacc[4][4];
#pragma unroll
        for (int i = 0; i < 4; i++)
#pragma unroll
            for (int j = 0; j < 4; j++) sacc[i][j] = 0.f;

#pragma unroll 8
        for (int k = 0; k < 128; k++) {
            float4 a = *(const float4*)&Qt[k * 68 + ty * 4];
            float4 bb = *(const float4*)&KV[k * 68 + tx * 4];
            float av[4] = {a.x, a.y, a.z, a.w};
            float bv[4] = {bb.x, bb.y, bb.z, bb.w};
#pragma unroll
            for (int i = 0; i < 4; i++)
#pragma unroll
                for (int j = 0; j < 4; j++)
                    sacc[i][j] = fmaf(av[i], bv[j], sacc[i][j]);
        }

        // online softmax per row (16-lane groups share a row set)
#pragma unroll
        for (int i = 0; i < 4; i++) {
            float mx = fmaxf(fmaxf(sacc[i][0], sacc[i][1]),
                             fmaxf(sacc[i][2], sacc[i][3]));
#pragma unroll
            for (int off = 8; off; off >>= 1)
                mx = fmaxf(mx, __shfl_xor_sync(0xffffffffu, mx, off));
            float mn = fmaxf(m_i[i], mx);
            float fac = __expf(m_i[i] - mn);
            float rs = 0.f;
#pragma unroll
            for (int j = 0; j < 4; j++) {
                float p = __expf(sacc[i][j] - mn);
                sacc[i][j] = p;
                rs += p;
            }
#pragma unroll
            for (int off = 8; off; off >>= 1)
                rs += __shfl_xor_sync(0xffffffffu, rs, off);
            l_i[i] = l_i[i] * fac + rs;
            m_i[i] = mn;
#pragma unroll
            for (int c = 0; c < 8; c++) acc[i][c] *= fac;
#pragma unroll
            for (int j = 0; j < 4; j++)
                Pt[(tx * 4 + j) * 68 + ty * 4 + i] = sacc[i][j];
        }
        __syncthreads();

        // V tile (natural layout)
        const float* Vt_g = Vg + (size_t)kt * 64 * HD;
#pragma unroll
        for (int i = 0; i < 8; i++) {
            int v = tid + i * 256;
            int r = v >> 5;
            int c4 = (v & 31) << 2;
            *(float4*)&KV[r * 132 + c4] = *(const float4*)(Vt_g + r * HD + c4);
        }
        __syncthreads();

        // O += P V  (64x128, K=64)
#pragma unroll 4
        for (int k = 0; k < 64; k++) {
            float4 a  = *(const float4*)&Pt[k * 68 + ty * 4];
            float4 b0 = *(const float4*)&KV[k * 132 + tx * 8];
            float4 b1 = *(const float4*)&KV[k * 132 + tx * 8 + 4];
            float av[4] = {a.x, a.y, a.z, a.w};
            float bv[8] = {b0.x, b0.y, b0.z, b0.w, b1.x, b1.y, b1.z, b1.w};
#pragma unroll
            for (int i = 0; i < 4; i++)
#pragma unroll
                for (int c = 0; c < 8; c++)
                    acc[i][c] = fmaf(av[i], bv[c], acc[i][c]);
        }
        __syncthreads();
    }

    // write to merged-head layout g_y[(b*S+s)*D + h*128 + d]
#pragma unroll
    for (int i = 0; i < 4; i++) {
        float invl = 1.0f / l_i[i];
        int sq = q0 + ty * 4 + i;
        float* op = g_y + ((size_t)(b * SEQ + sq) * DIMX) + h * HD + tx * 8;
        *(float4*)op = make_float4(acc[i][0] * invl, acc[i][1] * invl,
                                   acc[i][2] * invl, acc[i][3] * invl);
        *(float4*)(op + 4) = make_float4(acc[i][4] * invl, acc[i][5] * invl,
                                         acc[i][6] * invl, acc[i][7] * invl);
    }
}

// ---------------- launch ---------------------------------------------------
extern "C" void kernel_launch(void* const* d_in, const int* in_sizes, int n_in,
                              void* d_out, int out_size)
{
    const float* x     = (const float*)d_in[0];
    const float* wqkv  = (const float*)d_in[1];
    const float* wproj = (const float*)d_in[2];
    const float* qnw   = (const float*)d_in[3];
    const float* knw   = (const float*)d_in[4];
    float* out = (float*)d_out;

    static bool attr_set = false;
    if (!attr_set) {
        cudaFuncSetAttribute(attn_kernel,
                             cudaFuncAttributeMaxDynamicSharedMemorySize,
                             ATTN_SMEM_FLOATS * 4);
        attr_set = true;
    }

    // 1. QKV projection with scatter epilogue
    sgemm_kernel<<<dim3(3 * DIMX / BN, TOK / BM), 256>>>(
        x, wqkv, nullptr, TOK, 3 * DIMX, DIMX, 1);

    // 2. RMSNorm + RoPE on q,k (in place)
    norm_rope_kernel<<<(2 * BSZ * NH * SEQ) / 8, 256>>>(qnw, knw);

    // 3. attention -> g_y (merged-head layout)
    attn_kernel<<<dim3(SEQ / 64, BSZ * NH), 256, ATTN_SMEM_FLOATS * 4>>>();

    // 4. output projection
    sgemm_kernel<<<dim3(DIMX / BN, TOK / BM), 256>>>(
        nullptr, wproj, out, TOK, DIMX, DIMX, 0);
}

// round 5
// speedup vs baseline: 4.1028x; 4.1028x over previous
#include <cuda_runtime.h>
#include <math.h>

#define BSZ 4
#define SEQ 2048
#define DIMX 2048
#define NH 16
#define HD 128
#define TOK (BSZ*SEQ)   // 8192

// ---------------- scratch (device globals; no cudaMalloc allowed) ----------
__device__ float g_q[BSZ*NH*SEQ*HD];   // [bh][s][d]  fp32 then tf32 after norm
__device__ float g_k[BSZ*NH*SEQ*HD];
__device__ float g_v[BSZ*NH*SEQ*HD];   // fp32
__device__ float g_vt[BSZ*NH*HD*SEQ];  // [bh][d][s]  tf32 bits
__device__ float g_y[TOK*DIMX];        // attention out, [token][dim] fp32

// ---------------- helpers ---------------------------------------------------
__device__ __forceinline__ unsigned f2tf(float x) {
    unsigned u;
    asm("cvt.rna.tf32.f32 %0, %1;" : "=r"(u) : "f"(x));
    return u;
}
__device__ __forceinline__ void ldsm4(unsigned r[4], unsigned addr) {
    asm volatile("ldmatrix.sync.aligned.m8n8.x4.shared.b16 {%0,%1,%2,%3}, [%4];"
                 : "=r"(r[0]), "=r"(r[1]), "=r"(r[2]), "=r"(r[3]) : "r"(addr));
}
__device__ __forceinline__ void mma8(float d[4], const unsigned a[4], const unsigned b[2]) {
    asm volatile("mma.sync.aligned.m16n8k8.row.col.f32.tf32.tf32.f32 "
                 "{%0,%1,%2,%3}, {%4,%5,%6,%7}, {%8,%9}, {%0,%1,%2,%3};"
                 : "+f"(d[0]), "+f"(d[1]), "+f"(d[2]), "+f"(d[3])
                 : "r"(a[0]), "r"(a[1]), "r"(a[2]), "r"(a[3]), "r"(b[0]), "r"(b[1]));
}

// ---------------- tf32 GEMM: C[m][n] = sum_k A[m][k]*B[n][k] ----------------
// block 128x128, BK=32, 8 warps as 2(m)x4(n), warp tile 64x32 of m16n8k8.
// mode 0: plain store. mode 1: qkv scatter. A==nullptr -> use g_y.
__global__ __launch_bounds__(256)
void gemm_tf32_kernel(const float* __restrict__ A, const float* __restrict__ B,
                      float* __restrict__ C, int M, int N, int K, int mode)
{
    __shared__ __align__(16) unsigned s_a[128*36];
    __shared__ __align__(16) unsigned s_b[128*36];
    if (A == nullptr) A = g_y;

    const int tid = threadIdx.x;
    const int l = tid & 31, w = tid >> 5;
    const int wm = w >> 2, wn = w & 3;
    const int m0 = blockIdx.y * 128, n0 = blockIdx.x * 128;

    const int lr = tid >> 3;            // 0..31 (+32*i)
    const int lc = (tid & 7) << 2;      // 0..28

    const float* Ap = A + (size_t)m0 * K;
    const float* Bp = B + (size_t)n0 * K;

    float4 pa[4], pb[4];
#pragma unroll
    for (int i = 0; i < 4; i++) {
        pa[i] = *(const float4*)(Ap + (size_t)(lr + 32*i) * K + lc);
        pb[i] = *(const float4*)(Bp + (size_t)(lr + 32*i) * K + lc);
    }

    float acc[4][4][4];
#pragma unroll
    for (int a = 0; a < 4; a++)
#pragma unroll
        for (int b = 0; b < 4; b++)
#pragma unroll
            for (int v = 0; v < 4; v++) acc[a][b][v] = 0.f;

    const unsigned smA = (unsigned)__cvta_generic_to_shared(s_a);
    const unsigned smB = (unsigned)__cvta_generic_to_shared(s_b);
    const unsigned aAddr = smA + (((wm*64 + ((l>>3)&1)*8 + (l&7))*36 + ((l>>4)<<2)) << 2);
    const unsigned bAddr = smB + (((wn*32 + ((l>>4)<<3) + (l&7))*36 + (((l>>3)&1)<<2)) << 2);

    const int ntile = K / 32;
    for (int kt = 0; kt < ntile; kt++) {
#pragma unroll
        for (int i = 0; i < 4; i++) {
            uint4 ua = make_uint4(f2tf(pa[i].x), f2tf(pa[i].y), f2tf(pa[i].z), f2tf(pa[i].w));
            *(uint4*)&s_a[(lr + 32*i)*36 + lc] = ua;
            uint4 ub = make_uint4(f2tf(pb[i].x), f2tf(pb[i].y), f2tf(pb[i].z), f2tf(pb[i].w));
            *(uint4*)&s_b[(lr + 32*i)*36 + lc] = ub;
        }
        __syncthreads();

        if (kt + 1 < ntile) {
            const int ko = (kt + 1) * 32 + lc;
#pragma unroll
            for (int i = 0; i < 4; i++) {
                pa[i] = *(const float4*)(Ap + (size_t)(lr + 32*i) * K + ko);
                pb[i] = *(const float4*)(Bp + (size_t)(lr + 32*i) * K + ko);
            }
        }

#pragma unroll
        for (int ks = 0; ks < 4; ks++) {
            unsigned af[4][4], bf[2][4];
#pragma unroll
            for (int mt = 0; mt < 4; mt++)
                ldsm4(af[mt], aAddr + ((mt*16*36 + ks*8) << 2));
#pragma unroll
            for (int nb = 0; nb < 2; nb++)
                ldsm4(bf[nb], bAddr + ((nb*16*36 + ks*8) << 2));
#pragma unroll
            for (int mt = 0; mt < 4; mt++)
#pragma unroll
                for (int nt = 0; nt < 4; nt++)
                    mma8(acc[mt][nt], af[mt], &bf[nt>>1][(nt&1)*2]);
        }
        __syncthreads();
    }

    const int g = l >> 2, c = l & 3;
    if (mode == 0) {
#pragma unroll
        for (int mt = 0; mt < 4; mt++)
#pragma unroll
            for (int nt = 0; nt < 4; nt++) {
                int m = m0 + wm*64 + mt*16 + g;
                int n = n0 + wn*32 + nt*8 + 2*c;
                *(float2*)&C[(size_t)m*N + n]     = make_float2(acc[mt][nt][0], acc[mt][nt][1]);
                *(float2*)&C[(size_t)(m+8)*N + n] = make_float2(acc[mt][nt][2], acc[mt][nt][3]);
            }
    } else {
        const int which = n0 >> 11;
        const int h = (n0 >> 7) & 15;
        float* dst = (which == 0) ? g_q : (which == 1) ? g_k : g_v;
#pragma unroll
        for (int mt = 0; mt < 4; mt++)
#pragma unroll
            for (int nt = 0; nt < 4; nt++) {
                int m = m0 + wm*64 + mt*16 + g;
                int b_ = m >> 11, s = m & 2047;
                int d = wn*32 + nt*8 + 2*c;
                float* p = dst + (((size_t)(b_*NH + h)*SEQ + s)*HD + d);
                *(float2*)p            = make_float2(acc[mt][nt][0], acc[mt][nt][1]);
                *(float2*)(p + 8*HD)   = make_float2(acc[mt][nt][2], acc[mt][nt][3]);
            }
    }
}

// ---------------- RMSNorm + RoPE on q,k (in place, output tf32 bits) -------
__global__ void norm_rope_kernel(const float* __restrict__ qw,
                                 const float* __restrict__ kw)
{
    const int NROW = BSZ * NH * SEQ;
    int gw = (blockIdx.x * blockDim.x + threadIdx.x) >> 5;
    int lane = threadIdx.x & 31;
    int tensor = (gw >= NROW);
    int row = tensor ? gw - NROW : gw;
    float* base = (tensor ? g_k : g_q) + (size_t)row * HD;
    const float* w = tensor ? kw : qw;
    const int s = row & (SEQ - 1);
    const float qscale = tensor ? 1.0f : 0.08838834764831845f;  // 128^-0.5 on q only

    float4 v = *(const float4*)(base + lane * 4);
    float ss = v.x*v.x + v.y*v.y + v.z*v.z + v.w*v.w;
#pragma unroll
    for (int off = 16; off; off >>= 1)
        ss += __shfl_xor_sync(0xffffffffu, ss, off);
    const float inv = rsqrtf(ss * (1.0f / HD) + 1e-6f);

    const float4 wv = *(const float4*)(w + lane * 4);
    float xv[4];
    xv[0] = v.x * inv * wv.x; xv[1] = v.y * inv * wv.y;
    xv[2] = v.z * inv * wv.z; xv[3] = v.w * inv * wv.w;

    unsigned ov[4];
#pragma unroll
    for (int u = 0; u < 4; u++) {
        float other = __shfl_xor_sync(0xffffffffu, xv[u], 16);
        int i = ((lane & 15) << 2) + u;               // freq index 0..63
        float freq = exp2f(-5.0f * (float)i * (1.0f / 64.0f));  // 32^(-i/64)
        float ang = (float)s * freq;
        float sn, cs;
        sincosf(ang, &sn, &cs);
        float r = (lane < 16) ? (xv[u]*cs - other*sn) : (xv[u]*cs + other*sn);
        ov[u] = f2tf(r * qscale);
    }
    *(uint4*)(base + lane * 4) = make_uint4(ov[0], ov[1], ov[2], ov[3]);
}

// ---------------- V transpose: g_v[bh][s][d] -> g_vt[bh][d][s] (tf32) ------
__global__ void transpose_v_kernel()
{
    __shared__ float t[32][33];
    const int bh = blockIdx.z;
    const int s0 = blockIdx.x * 32, d0 = blockIdx.y * 32;
    const int tx = threadIdx.x, ty = threadIdx.y;
    const float* src = g_v + (size_t)bh * SEQ * HD;
    float* dst = g_vt + (size_t)bh * HD * SEQ;
#pragma unroll
    for (int j = 0; j < 4; j++)
        t[ty + 8*j][tx] = src[(size_t)(s0 + ty + 8*j) * HD + d0 + tx];
    __syncthreads();
#pragma unroll
    for (int j = 0; j < 4; j++)
        dst[(size_t)(d0 + ty + 8*j) * SEQ + s0 + tx] =
            __uint_as_float(f2tf(t[tx][ty + 8*j]));
}

// ---------------- flash attention (tf32 mma) --------------------------------
// grid (SEQ/128, BSZ*NH), block 256 (8 warps). Warp w owns q rows 16w..16w+15.
// per kt: 64 keys. S warp tile 16x64 (nt=8), PV warp tile 16x128 (nt=16).
#define ATTN_SMEM_BYTES ((128*132 + 64*132 + 128*68 + 128*68) * 4)

__global__ __launch_bounds__(256)
void attn_kernel()
{
    extern __shared__ __align__(16) float sm[];
    float* Qs = sm;                       // [q:128][132]
    float* Ks = sm + 128*132;             // [key:64][132]
    float* Vt = Ks + 64*132;              // [d:128][68]
    float* Ps = Vt + 128*68;              // [q:128][68]

    const int tid = threadIdx.x;
    const int w = tid >> 5, l = tid & 31;
    const int g = l >> 2, c = l & 3;
    const int bh = blockIdx.y, b = bh >> 4, h = bh & 15;
    const int q0 = blockIdx.x * 128;
    const float* Qg = g_q + ((size_t)bh * SEQ + q0) * HD;
    const float* Kg = g_k + (size_t)bh * SEQ * HD;
    const float* Vg = g_vt + (size_t)bh * HD * SEQ;

    // load Q tile (already tf32 + scaled): 128x128
#pragma unroll
    for (int i = 0; i < 16; i++) {
        int v = tid + i * 256;
        int r = v >> 5, cc = (v & 31) << 2;
        *(float4*)&Qs[r*132 + cc] = *(const float4*)(Qg + (size_t)r * HD + cc);
    }

    const unsigned smBase = (unsigned)__cvta_generic_to_shared(sm);
    const unsigned qAddr = smBase + (((16*w + ((l>>3)&1)*8 + (l&7))*132 + ((l>>4)<<2)) << 2);
    const unsigned kAddr = smBase + ((128*132 + (((l>>4)<<3) + (l&7))*132 + (((l>>3)&1)<<2)) << 2);
    const unsigned vAddr = smBase + ((128*132 + 64*132 + (((l>>4)<<3) + (l&7))*68 + (((l>>3)&1)<<2)) << 2);
    const unsigned pAddr = smBase + ((128*132 + 64*132 + 128*68 + (16*w + ((l>>3)&1)*8 + (l&7))*68 + ((l>>4)<<2)) << 2);

    float oacc[16][4];
#pragma unroll
    for (int i = 0; i < 16; i++)
#pragma unroll
        for (int v = 0; v < 4; v++) oacc[i][v] = 0.f;
    float mrow[2] = {-1e30f, -1e30f};
    float lrow[2] = {0.f, 0.f};

    for (int kt = 0; kt < SEQ/64; kt++) {
        __syncthreads();   // protect Ks/Vt while any warp still in prior PV
        // K tile 64x128 + Vt tile 128x64 (both tf32 bits already)
#pragma unroll
        for (int i = 0; i < 8; i++) {
            int v = tid + i * 256;
            int r = v >> 5, cc = (v & 31) << 2;
            *(float4*)&Ks[r*132 + cc] = *(const float4*)(Kg + (size_t)(kt*64 + r)*HD + cc);
        }
#pragma unroll
        for (int i = 0; i < 8; i++) {
            int v = tid + i * 256;
            int dr = v >> 4, cc = (v & 15) << 2;
            *(float4*)&Vt[dr*68 + cc] = *(const float4*)(Vg + (size_t)dr * SEQ + kt*64 + cc);
        }
        __syncthreads();

        // S = Q K^T  : warp 16q x 64n, K=128
        float sacc[8][4];
#pragma unroll
        for (int nt = 0; nt < 8; nt++)
#pragma unroll
            for (int v = 0; v < 4; v++) sacc[nt][v] = 0.f;

#pragma unroll
        for (int ks = 0; ks < 16; ks++) {
            unsigned qa[4], kb[4][4];
            ldsm4(qa, qAddr + ((ks*8) << 2));
#pragma unroll
            for (int np = 0; np < 4; np++)
                ldsm4(kb[np], kAddr + ((np*16*132 + ks*8) << 2));
#pragma unroll
            for (int nt = 0; nt < 8; nt++)
                mma8(sacc[nt], qa, &kb[nt>>1][(nt&1)*2]);
        }

        // online softmax, warp-local (rows g and g+8)
#pragma unroll
        for (int hh = 0; hh < 2; hh++) {
            float mx = -1e30f;
#pragma unroll
            for (int nt = 0; nt < 8; nt++)
                mx = fmaxf(mx, fmaxf(sacc[nt][2*hh], sacc[nt][2*hh+1]));
            mx = fmaxf(mx, __shfl_xor_sync(0xffffffffu, mx, 1));
            mx = fmaxf(mx, __shfl_xor_sync(0xffffffffu, mx, 2));
            float mn = fmaxf(mrow[hh], mx);
            float fac = __expf(mrow[hh] - mn);
            float rs = 0.f;
#pragma unroll
            for (int nt = 0; nt < 8; nt++) {
                float p0 = __expf(sacc[nt][2*hh]   - mn);
                float p1 = __expf(sacc[nt][2*hh+1] - mn);
                sacc[nt][2*hh] = p0; sacc[nt][2*hh+1] = p1;
                rs += p0 + p1;
                // store P (tf32) — row 16w+g+8hh, col nt*8+2c
                *(float2*)&Ps[(16*w + g + 8*hh)*68 + nt*8 + 2*c] =
                    make_float2(__uint_as_float(f2tf(p0)), __uint_as_float(f2tf(p1)));
            }
            rs += __shfl_xor_sync(0xffffffffu, rs, 1);
            rs += __shfl_xor_sync(0xffffffffu, rs, 2);
            lrow[hh] = lrow[hh] * fac + rs;
            mrow[hh] = mn;
#pragma unroll
            for (int nt = 0; nt < 16; nt++) {
                oacc[nt][2*hh]   *= fac;
                oacc[nt][2*hh+1] *= fac;
            }
        }
        __syncwarp();

        // O += P V : warp 16q x 128d, K=64
#pragma unroll
        for (int ks = 0; ks < 8; ks++) {
            unsigned pa[4];
            ldsm4(pa, pAddr + ((ks*8) << 2));
#pragma unroll
            for (int np = 0; np < 8; np++) {
                unsigned vb[4];
                ldsm4(vb, vAddr + ((np*16*68 + ks*8) << 2));
                mma8(oacc[2*np],   pa, &vb[0]);
                mma8(oacc[2*np+1], pa, &vb[2]);
            }
        }
    }

    // epilogue: divide by l, store merged-head
    const float inv0 = 1.0f / lrow[0], inv1 = 1.0f / lrow[1];
    const int sq = q0 + 16*w + g;
#pragma unroll
    for (int nt = 0; nt < 16; nt++) {
        int d = nt*8 + 2*c;
        float* p0 = g_y + (size_t)(b*SEQ + sq) * DIMX + h*HD + d;
        float* p1 = g_y + (size_t)(b*SEQ + sq + 8) * DIMX + h*HD + d;
        *(float2*)p0 = make_float2(oacc[nt][0]*inv0, oacc[nt][1]*inv0);
        *(float2*)p1 = make_float2(oacc[nt][2]*inv1, oacc[nt][3]*inv1);
    }
}

// ---------------- launch ----------------------------------------------------
extern "C" void kernel_launch(void* const* d_in, const int* in_sizes, int n_in,
                              void* d_out, int out_size)
{
    const float* x     = (const float*)d_in[0];
    const float* wqkv  = (const float*)d_in[1];
    const float* wproj = (const float*)d_in[2];
    const float* qnw   = (const float*)d_in[3];
    const float* knw   = (const float*)d_in[4];
    float* out = (float*)d_out;

    static bool attr_set = false;
    if (!attr_set) {
        cudaFuncSetAttribute(attn_kernel,
                             cudaFuncAttributeMaxDynamicSharedMemorySize,
                             ATTN_SMEM_BYTES);
        attr_set = true;
    }

    // 1. QKV projection (tf32 MMA) with qkv scatter
    gemm_tf32_kernel<<<dim3(3*DIMX/128, TOK/128), 256>>>(
        x, wqkv, nullptr, TOK, 3*DIMX, DIMX, 1);

    // 2. RMSNorm + RoPE (+ q-scale, tf32 round) in place
    norm_rope_kernel<<<(2*BSZ*NH*SEQ)/8, 256>>>(qnw, knw);

    // 3. V transpose -> [bh][d][s] (tf32)
    transpose_v_kernel<<<dim3(SEQ/32, HD/32, BSZ*NH), dim3(32, 8)>>>();

    // 4. attention (tf32 MMA flash) -> g_y merged-head
    attn_kernel<<<dim3(SEQ/128, BSZ*NH), 256, ATTN_SMEM_BYTES>>>();

    // 5. output projection (tf32 MMA)
    gemm_tf32_kernel<<<dim3(DIMX/128, TOK/128), 256>>>(
        nullptr, wproj, out, TOK, DIMX, DIMX, 0);
}